// round 13
// baseline (speedup 1.0000x reference)
#include <cuda_runtime.h>
#include <cuda_fp16.h>

#define DINL __device__ __forceinline__

// ---------------------------------------------------------------------------
// GFocalV2 head (sm_103): fused 3-layer MLPs via mma.sync.m16n8k16 + ldmatrix.
// 512 threads / 16 warps, warp tile 64x32, full 128x256 layer per sweep,
// layer weights fully resident, in-place SA activations. Round 12: quality
// and cls-dot parallelized across all 512 threads with shuffle reductions.
// ---------------------------------------------------------------------------

namespace cfg {
constexpr int P    = 32 * 96 * 96;   // 294912
constexpr int TM   = 128;            // rows per CTA
constexpr int NBLK = P / TM;         // 2304
constexpr int HHALF = 16384;         // halves per 32KB piece
constexpr int NH   = 18;             // pieces in weight cache

// dynamic smem (bytes)
constexpr int SA    = 0;             // 128x256 f16 blocked SW128 (64 KB), in-place I/O
constexpr int SB    = 65536;         // 4 x 32KB weight pieces (full layer)
constexpr int SBIAS = 196608;        // rb1 +0, rb2 +1024, cb1 +2048, cb2 +3072, rb3 +4096
constexpr int SSTAT = SBIAS + 4608;  // 128*21 f32
constexpr int SQW1  = SSTAT + 10752;
constexpr int SQB1  = SQW1 + 5120;
constexpr int SQW2  = SQB1 + 256;
constexpr int SCW3  = SQW2 + 256;
constexpr int SQUAL = SCW3 + 1024;
constexpr int SSC   = SQUAL + 512;
constexpr int SMEMB = SSC + 16;      // ~219 KB
}  // namespace cfg

__device__ __align__(16) __half g_wh[cfg::NH * cfg::HHALF];

// --------------------- weight fp32 -> fp16 pre-swizzled --------------------
__global__ void convert_weights_kernel(const float* __restrict__ cw1,
                                       const float* __restrict__ cw2,
                                       const float* __restrict__ rw1,
                                       const float* __restrict__ rw2,
                                       const float* __restrict__ rw3) {
    int i = blockIdx.x * 512 + threadIdx.x;   // 0..294911
    int sc = i >> 15;
    int e  = i & 32767;
    int r  = e >> 8, c = e & 255;
    float v = 0.f;
    if (sc < 2)       v = rw1[(sc * 128 + r) * 256 + c];
    else if (sc < 4)  v = rw2[((sc - 2) * 128 + r) * 256 + c];
    else if (sc < 5)  { if (r < 68) v = rw3[r * 256 + c]; }
    else if (sc < 7)  v = cw1[((sc - 5) * 128 + r) * 256 + c];
    else              v = cw2[((sc - 7) * 128 + r) * 256 + c];
    int byte = ((r >> 3) + (c >> 6) * 16) * 1024 + (r & 7) * 128 + (c & 63) * 2;
    byte ^= (r & 7) << 4;
    g_wh[sc * 32768 + (byte >> 1)] = __float2half(v);
}

// ------------------------------ PTX helpers --------------------------------
DINL unsigned smem_u32(const void* p) {
    unsigned a;
    asm("{ .reg .u64 t; cvta.to.shared.u64 t, %1; cvt.u32.u64 %0, t; }"
        : "=r"(a) : "l"(p));
    return a;
}
DINL void ldm4(unsigned r[4], unsigned addr) {
    asm volatile("ldmatrix.sync.aligned.m8n8.x4.shared.b16 {%0,%1,%2,%3}, [%4];"
                 : "=r"(r[0]), "=r"(r[1]), "=r"(r[2]), "=r"(r[3]) : "r"(addr));
}
DINL void mma4(float d[4], const unsigned a[4], unsigned b0, unsigned b1) {
    asm volatile(
        "mma.sync.aligned.m16n8k16.row.col.f32.f16.f16.f32 "
        "{%0,%1,%2,%3}, {%4,%5,%6,%7}, {%8,%9}, {%0,%1,%2,%3};\n"
        : "+f"(d[0]), "+f"(d[1]), "+f"(d[2]), "+f"(d[3])
        : "r"(a[0]), "r"(a[1]), "r"(a[2]), "r"(a[3]), "r"(b0), "r"(b1));
}
#define CP_COMMIT() asm volatile("cp.async.commit_group;" ::: "memory")
template <int N> DINL void cp_wait() {
    asm volatile("cp.async.wait_group %0;" :: "n"(N) : "memory");
}

// ----------------------------- staging -------------------------------------
DINL void stage_layer(int h0, int npieces, unsigned sbm, int tid) {
    const __half* g = g_wh + (size_t)h0 * cfg::HHALF + tid * 8;
    unsigned dst = sbm + cfg::SB + tid * 16;
    for (int j = 0; j < npieces * 4; ++j)
        asm volatile("cp.async.cg.shared.global [%0], [%1], 16;"
                     :: "r"(dst + j * 8192), "l"(g + j * 4096) : "memory");
    CP_COMMIT();
}

// 128 rows x 256 f32 -> f16 into SA, blocked SW128 (512 threads)
DINL void stage_x(const float* __restrict__ x, char* smem, int tid) {
    #pragma unroll
    for (int i = tid; i < 4096; i += 512) {
        int r = i >> 5, u = i & 31;
        const float4* src = (const float4*)(x + (size_t)r * 256 + u * 8);
        float4 v0 = src[0], v1 = src[1];
        __half2 h0 = __floats2half2_rn(v0.x, v0.y);
        __half2 h1 = __floats2half2_rn(v0.z, v0.w);
        __half2 h2 = __floats2half2_rn(v1.x, v1.y);
        __half2 h3 = __floats2half2_rn(v1.z, v1.w);
        int byte = ((r >> 3) + (u >> 3) * 16) * 1024 + (r & 7) * 128 + (u & 7) * 16;
        byte ^= (r & 7) << 4;
        uint4 pk;
        pk.x = *(unsigned*)&h0; pk.y = *(unsigned*)&h1;
        pk.z = *(unsigned*)&h2; pk.w = *(unsigned*)&h3;
        *(uint4*)(smem + cfg::SA + byte) = pk;
    }
}

// ---------------- full-layer 128x256 GEMM, warp tile 64x32 -----------------
template <int NP>   // 4 = full 256-col layer, 2 = reg layer (only cols<96 live)
DINL void mma_layer(unsigned aBase, unsigned bBase, float acc[4][4][4],
                    int lane, int wm, int wn) {
    #pragma unroll
    for (int i = 0; i < 4; ++i)
        #pragma unroll
        for (int j = 0; j < 4; ++j)
            #pragma unroll
            for (int k = 0; k < 4; ++k) acc[i][j][k] = 0.f;
    if (NP == 2 && wn >= 3) return;   // reg layer: cols >= 96 all dead

    const int la7 = lane & 7, lb3 = (lane >> 3) & 1, lb4 = (lane >> 4) & 1;
    unsigned rowA[4], rowB[2];
    #pragma unroll
    for (int mi = 0; mi < 4; ++mi) {
        int R = wm * 64 + mi * 16 + lb3 * 8 + la7;
        rowA[mi] = aBase + (unsigned)((R >> 3) * 1024 + la7 * 128);
    }
    const unsigned bsel = (wn >= 4) ? 65536u : 0u;
    #pragma unroll
    for (int np = 0; np < 2; ++np) {
        int R = (wn & 3) * 32 + np * 16 + lb4 * 8 + la7;
        rowB[np] = bBase + bsel + (unsigned)((R >> 3) * 1024 + la7 * 128);
    }
    #pragma unroll
    for (int k0 = 0; k0 < 16; ++k0) {
        int qa  = 2 * k0 + lb4;
        int qbl = 2 * (k0 & 7) + lb3;
        unsigned ca = (unsigned)(((qa >> 3) << 14) + (((qa & 7) ^ la7) << 4));
        unsigned cb = (unsigned)((k0 >= 8 ? 32768 : 0) +
                                 ((qbl >> 3) << 14) + (((qbl & 7) ^ la7) << 4));
        unsigned a0[4], a1[4], a2[4], a3[4], b0[4], b1[4];
        ldm4(a0, rowA[0] + ca);
        ldm4(a1, rowA[1] + ca);
        ldm4(a2, rowA[2] + ca);
        ldm4(a3, rowA[3] + ca);
        ldm4(b0, rowB[0] + cb);
        ldm4(b1, rowB[1] + cb);
        mma4(acc[0][0], a0, b0[0], b0[1]); mma4(acc[0][1], a0, b0[2], b0[3]);
        mma4(acc[0][2], a0, b1[0], b1[1]); mma4(acc[0][3], a0, b1[2], b1[3]);
        mma4(acc[1][0], a1, b0[0], b0[1]); mma4(acc[1][1], a1, b0[2], b0[3]);
        mma4(acc[1][2], a1, b1[0], b1[1]); mma4(acc[1][3], a1, b1[2], b1[3]);
        mma4(acc[2][0], a2, b0[0], b0[1]); mma4(acc[2][1], a2, b0[2], b0[3]);
        mma4(acc[2][2], a2, b1[0], b1[1]); mma4(acc[2][3], a2, b1[2], b1[3]);
        mma4(acc[3][0], a3, b0[0], b0[1]); mma4(acc[3][1], a3, b0[2], b0[3]);
        mma4(acc[3][2], a3, b1[0], b1[1]); mma4(acc[3][3], a3, b1[2], b1[3]);
    }
}

// bias + relu -> f16 IN PLACE into SA (blocked SW128), full 256 cols
DINL void epi_hidden(const float acc[4][4][4], char* sOut, const float* bias,
                     int lane, int wm, int wn) {
    #pragma unroll
    for (int mi = 0; mi < 4; ++mi) {
        int R = wm * 64 + mi * 16 + (lane >> 2);
        #pragma unroll
        for (int nj = 0; nj < 4; ++nj) {
            int C = wn * 32 + nj * 8 + (lane & 3) * 2;
            float b0 = bias[C], b1 = bias[C + 1];
            __half2 lo = __floats2half2_rn(fmaxf(acc[mi][nj][0] + b0, 0.f),
                                           fmaxf(acc[mi][nj][1] + b1, 0.f));
            __half2 hi = __floats2half2_rn(fmaxf(acc[mi][nj][2] + b0, 0.f),
                                           fmaxf(acc[mi][nj][3] + b1, 0.f));
            int byte = ((R >> 3) + (C >> 6) * 16) * 1024 + (R & 7) * 128 + (C & 63) * 2;
            byte ^= (R & 7) << 4;
            *(__half2*)(sOut + byte) = lo;
            *(__half2*)(sOut + byte + 1024) = hi;
        }
    }
}

// reg-pred epilogue: fp32 (cols < 68) IN PLACE into SA (stride 68) + global
DINL void epi_reg(const float acc[4][4][4], float* sReg, const float* bias,
                  float* __restrict__ gReg, int row0, int lane, int wm, int wn) {
    if (wn >= 3) return;
    #pragma unroll
    for (int mi = 0; mi < 4; ++mi) {
        int R = wm * 64 + mi * 16 + (lane >> 2);
        #pragma unroll
        for (int nj = 0; nj < 4; ++nj) {
            int C = wn * 32 + nj * 8 + (lane & 3) * 2;
            if (C < 68) {
                float b0 = bias[C], b1 = bias[C + 1];
                float2 lo = make_float2(acc[mi][nj][0] + b0, acc[mi][nj][1] + b1);
                float2 hi = make_float2(acc[mi][nj][2] + b0, acc[mi][nj][3] + b1);
                *(float2*)(sReg + R * 68 + C) = lo;
                *(float2*)(sReg + (R + 8) * 68 + C) = hi;
                *(float2*)(gReg + (size_t)(row0 + R) * 68 + C) = lo;
                *(float2*)(gReg + (size_t)(row0 + R + 8) * 68 + C) = hi;
            }
        }
    }
}

// ------------------------------ main kernel --------------------------------
__global__ __launch_bounds__(512, 1)
void gfocal_head_kernel(const float* __restrict__ x,
                        const float* __restrict__ cb1, const float* __restrict__ cb2,
                        const float* __restrict__ cw3, const float* __restrict__ cb3,
                        const float* __restrict__ rb1, const float* __restrict__ rb2,
                        const float* __restrict__ rb3,
                        const float* __restrict__ qw1, const float* __restrict__ qb1,
                        const float* __restrict__ qw2, const float* __restrict__ qb2,
                        float* __restrict__ out) {
    using namespace cfg;
    extern __shared__ char smem[];
    const unsigned sbm = smem_u32(smem);
    const int tid = threadIdx.x, w = tid >> 5, lane = tid & 31;
    const int wm = w >> 3, wn = w & 7;
    const int row0 = blockIdx.x * TM;

    float* out_cls = out;
    float* out_box = out + (size_t)P;
    float* out_reg = out + (size_t)P * 5;

    const float* bias = (const float*)(smem + SBIAS);

    // ---- prolog: prefetch L0 weights, small weights, stage X ----
    stage_layer(0, 4, sbm, tid);
    if (tid < 256) {
        float* fb = (float*)(smem + SBIAS);
        fb[tid] = rb1[tid]; fb[256 + tid] = rb2[tid];
        fb[512 + tid] = cb1[tid]; fb[768 + tid] = cb2[tid];
        if (tid < 68) fb[1024 + tid] = rb3[tid];
        ((float*)(smem + SCW3))[tid] = cw3[tid];
        if (tid < 64) { ((float*)(smem + SQB1))[tid] = qb1[tid];
                        ((float*)(smem + SQW2))[tid] = qw2[tid]; }
        if (tid == 0) { ((float*)(smem + SSC))[0] = qb2[0];
                        ((float*)(smem + SSC))[1] = cb3[0]; }
    }
    {
        float* q1 = (float*)(smem + SQW1);
        for (int i = tid; i < 1280; i += 512) q1[i] = qw1[i];
    }
    stage_x(x + (size_t)row0 * 256, smem, tid);

    float acc[4][4][4];

    // ---------------- regression branch ----------------
    cp_wait<0>(); __syncthreads();
    mma_layer<4>(sbm + SA, sbm + SB, acc, lane, wm, wn);   // X @ rw1^T
    __syncthreads();
    stage_layer(4, 4, sbm, tid);                           // prefetch rw2
    epi_hidden(acc, smem + SA, bias, lane, wm, wn);        // SA = h1r

    cp_wait<0>(); __syncthreads();
    mma_layer<4>(sbm + SA, sbm + SB, acc, lane, wm, wn);   // h1 @ rw2^T
    __syncthreads();
    stage_layer(8, 2, sbm, tid);                           // prefetch rw3
    epi_hidden(acc, smem + SA, bias + 256, lane, wm, wn);  // SA = h2r

    cp_wait<0>(); __syncthreads();
    mma_layer<2>(sbm + SA, sbm + SB, acc, lane, wm, wn);   // h2 @ rw3^T
    __syncthreads();
    stage_layer(10, 4, sbm, tid);                          // prefetch cw1
    epi_reg(acc, (float*)(smem + SA), bias + 1024, out_reg, row0, lane, wm, wn);
    __syncthreads();

    // ---- stats: softmax, box, top-4 -> sStat (thread = (row, direction)) ----
    {
        int row = tid >> 2, d = tid & 3;
        const float* rp = (const float*)(smem + SA) + row * 68 + d * 17;
        float* sStat = (float*)(smem + SSTAT);
        float pb[17];
        float mx = -1e30f;
        #pragma unroll
        for (int b = 0; b < 17; ++b) { pb[b] = rp[b]; mx = fmaxf(mx, pb[b]); }
        float s = 0.f, sbi = 0.f;
        #pragma unroll
        for (int b = 0; b < 17; ++b) {
            float e = __expf(pb[b] - mx);
            pb[b] = e; s += e; sbi += e * (float)b;
        }
        float inv = 1.f / s;
        out_box[(size_t)(row0 + row) * 4 + d] = sbi * inv * (1.f / 16.f);
        unsigned mask = 0; float tsum = 0.f;
        #pragma unroll
        for (int j = 0; j < 4; ++j) {
            float m = -1e30f; int mi = 0;
            #pragma unroll
            for (int b = 0; b < 17; ++b) {
                bool ok = !((mask >> b) & 1u) && (pb[b] > m);
                if (ok) { m = pb[b]; mi = b; }
            }
            mask |= (1u << mi);
            tsum += m;
            sStat[row * 21 + d * 5 + j] = m * inv;
        }
        sStat[row * 21 + d * 5 + 4] = tsum * inv * 0.25f;
    }
    __syncthreads();

    // ---- quality on ALL 512 threads: 4 threads/row, 16 hidden units each ----
    {
        int row = tid >> 2, sub = tid & 3;
        const float* st = (const float*)(smem + SSTAT) + row * 21;
        const float* q1 = (const float*)(smem + SQW1);
        const float* qb = (const float*)(smem + SQB1);
        const float* q2 = (const float*)(smem + SQW2);
        float stv[20];
        #pragma unroll
        for (int c = 0; c < 20; ++c) stv[c] = st[c];
        float q = 0.f;
        #pragma unroll 4
        for (int oo = 0; oo < 16; ++oo) {
            int o = sub * 16 + oo;
            float h = qb[o];
            #pragma unroll
            for (int c = 0; c < 20; ++c) h += q1[o * 20 + c] * stv[c];
            q += q2[o] * fmaxf(h, 0.f);
        }
        q += __shfl_xor_sync(0xFFFFFFFF, q, 1);
        q += __shfl_xor_sync(0xFFFFFFFF, q, 2);
        if (sub == 0) {
            float qs = q + ((const float*)(smem + SSC))[0];
            ((float*)(smem + SQUAL))[row] = 1.f / (1.f + __expf(-qs));
        }
    }
    __syncthreads();
    stage_x(x + (size_t)row0 * 256, smem, tid);            // SA = X again

    // ---------------- classification branch ----------------
    cp_wait<0>(); __syncthreads();
    mma_layer<4>(sbm + SA, sbm + SB, acc, lane, wm, wn);   // X @ cw1^T
    __syncthreads();
    stage_layer(14, 4, sbm, tid);                          // prefetch cw2
    epi_hidden(acc, smem + SA, bias + 512, lane, wm, wn);  // SA = h1c

    cp_wait<0>(); __syncthreads();
    mma_layer<4>(sbm + SA, sbm + SB, acc, lane, wm, wn);   // h1 @ cw2^T
    __syncthreads();
    epi_hidden(acc, smem + SA, bias + 768, lane, wm, wn);  // SA = h2c
    __syncthreads();

    // ---- cls L3 on ALL 512 threads: 4 threads/row, one 64-col group each ----
    {
        int row = tid >> 2, sub = tid & 3, r7 = row & 7;
        unsigned rbase = (unsigned)((row >> 3) * 1024 + r7 * 128 + sub * 16384);
        const float* w3 = (const float*)(smem + SCW3) + sub * 64;
        float a = 0.f;
        #pragma unroll
        for (int u = 0; u < 8; ++u) {
            const __half2* p = (const __half2*)(smem + SA + rbase + ((u ^ r7) << 4));
            const float* wseg = w3 + u * 8;
            #pragma unroll
            for (int j = 0; j < 4; ++j) {
                float2 v = __half22float2(p[j]);
                a += v.x * wseg[2 * j] + v.y * wseg[2 * j + 1];
            }
        }
        a += __shfl_xor_sync(0xFFFFFFFF, a, 1);
        a += __shfl_xor_sync(0xFFFFFFFF, a, 2);
        if (sub == 0) {
            float s = a + ((const float*)(smem + SSC))[1];
            float csig = 1.f / (1.f + __expf(-s));
            out_cls[row0 + row] = csig * ((const float*)(smem + SQUAL))[row];
        }
    }
}

// ------------------------------ launcher -----------------------------------
extern "C" void kernel_launch(void* const* d_in, const int* in_sizes, int n_in,
                              void* d_out, int out_size) {
    const float* x   = (const float*)d_in[0];
    const float* cw1 = (const float*)d_in[1];
    const float* cb1 = (const float*)d_in[2];
    const float* cw2 = (const float*)d_in[3];
    const float* cb2 = (const float*)d_in[4];
    const float* cw3 = (const float*)d_in[5];
    const float* cb3 = (const float*)d_in[6];
    const float* rw1 = (const float*)d_in[7];
    const float* rb1 = (const float*)d_in[8];
    const float* rw2 = (const float*)d_in[9];
    const float* rb2 = (const float*)d_in[10];
    const float* rw3 = (const float*)d_in[11];
    const float* rb3 = (const float*)d_in[12];
    const float* qw1 = (const float*)d_in[13];
    const float* qb1 = (const float*)d_in[14];
    const float* qw2 = (const float*)d_in[15];
    const float* qb2 = (const float*)d_in[16];
    float* out = (float*)d_out;

    cudaFuncSetAttribute(gfocal_head_kernel,
                         cudaFuncAttributeMaxDynamicSharedMemorySize, cfg::SMEMB);

    convert_weights_kernel<<<cfg::NH * cfg::HHALF / 512, 512>>>(cw1, cw2, rw1, rw2, rw3);
    gfocal_head_kernel<<<cfg::NBLK, 512, cfg::SMEMB>>>(
        x, cb1, cb2, cw3, cb3, rb1, rb2, rb3, qw1, qb1, qw2, qb2, out);
}

// round 14
// speedup vs baseline: 1.2978x; 1.2978x over previous
#include <cuda_runtime.h>
#include <cuda_fp16.h>

#define DINL __device__ __forceinline__

// ---------------------------------------------------------------------------
// GFocalV2 head (sm_103): fused 3-layer MLPs via mma.sync.m16n8k16 + ldmatrix.
// 512 threads / 16 warps, warp tile 64x32, full 128x256 layer per sweep,
// layer weights fully resident, in-place SA activations. Round 14: K-half
// split-group staging pipelined into the MMA k-loop; dead reg-layer MMA skipped.
// ---------------------------------------------------------------------------

namespace cfg {
constexpr int P    = 32 * 96 * 96;   // 294912
constexpr int TM   = 128;            // rows per CTA
constexpr int NBLK = P / TM;         // 2304
constexpr int HHALF = 16384;         // halves per 32KB piece
constexpr int NH   = 18;             // pieces in weight cache

// dynamic smem (bytes)
constexpr int SA    = 0;             // 128x256 f16 blocked SW128 (64 KB), in-place I/O
constexpr int SB    = 65536;         // 4 x 32KB weight pieces (full layer)
constexpr int SBIAS = 196608;        // rb1 +0, rb2 +1024, cb1 +2048, cb2 +3072, rb3 +4096
constexpr int SSTAT = SBIAS + 4608;  // 128*21 f32
constexpr int SQW1  = SSTAT + 10752;
constexpr int SQB1  = SQW1 + 5120;
constexpr int SQW2  = SQB1 + 256;
constexpr int SCW3  = SQW2 + 256;
constexpr int SQUAL = SCW3 + 1024;
constexpr int SSC   = SQUAL + 512;
constexpr int SMEMB = SSC + 16;      // ~219 KB
}  // namespace cfg

__device__ __align__(16) __half g_wh[cfg::NH * cfg::HHALF];

// --------------------- weight fp32 -> fp16 pre-swizzled --------------------
__global__ void convert_weights_kernel(const float* __restrict__ cw1,
                                       const float* __restrict__ cw2,
                                       const float* __restrict__ rw1,
                                       const float* __restrict__ rw2,
                                       const float* __restrict__ rw3) {
    int i = blockIdx.x * 512 + threadIdx.x;   // 0..294911
    int sc = i >> 15;
    int e  = i & 32767;
    int r  = e >> 8, c = e & 255;
    float v = 0.f;
    if (sc < 2)       v = rw1[(sc * 128 + r) * 256 + c];
    else if (sc < 4)  v = rw2[((sc - 2) * 128 + r) * 256 + c];
    else if (sc < 5)  { if (r < 68) v = rw3[r * 256 + c]; }
    else if (sc < 7)  v = cw1[((sc - 5) * 128 + r) * 256 + c];
    else              v = cw2[((sc - 7) * 128 + r) * 256 + c];
    int byte = ((r >> 3) + (c >> 6) * 16) * 1024 + (r & 7) * 128 + (c & 63) * 2;
    byte ^= (r & 7) << 4;
    g_wh[sc * 32768 + (byte >> 1)] = __float2half(v);
}

// ------------------------------ PTX helpers --------------------------------
DINL unsigned smem_u32(const void* p) {
    unsigned a;
    asm("{ .reg .u64 t; cvta.to.shared.u64 t, %1; cvt.u32.u64 %0, t; }"
        : "=r"(a) : "l"(p));
    return a;
}
DINL void ldm4(unsigned r[4], unsigned addr) {
    asm volatile("ldmatrix.sync.aligned.m8n8.x4.shared.b16 {%0,%1,%2,%3}, [%4];"
                 : "=r"(r[0]), "=r"(r[1]), "=r"(r[2]), "=r"(r[3]) : "r"(addr));
}
DINL void mma4(float d[4], const unsigned a[4], unsigned b0, unsigned b1) {
    asm volatile(
        "mma.sync.aligned.m16n8k16.row.col.f32.f16.f16.f32 "
        "{%0,%1,%2,%3}, {%4,%5,%6,%7}, {%8,%9}, {%0,%1,%2,%3};\n"
        : "+f"(d[0]), "+f"(d[1]), "+f"(d[2]), "+f"(d[3])
        : "r"(a[0]), "r"(a[1]), "r"(a[2]), "r"(a[3]), "r"(b0), "r"(b1));
}
#define CP_COMMIT() asm volatile("cp.async.commit_group;" ::: "memory")
template <int N> DINL void cp_wait() {
    asm volatile("cp.async.wait_group %0;" :: "n"(N) : "memory");
}

// ----------------------------- staging -------------------------------------
// Stage a layer (npieces x 32KB) in TWO commit groups:
//   G1 = even pieces (K-lo of each superchunk, needed for k0 < 8)
//   G2 = odd pieces  (K-hi, needed for k0 >= 8)
template <int NPIECES>
DINL void stage_layer2(int h0, unsigned sbm, int tid) {
    const __half* g = g_wh + (size_t)h0 * cfg::HHALF + tid * 8;
    unsigned dst = sbm + cfg::SB + tid * 16;
    #pragma unroll
    for (int p = 0; p < NPIECES; p += 2)
        #pragma unroll
        for (int j = 0; j < 4; ++j) {
            int jj = p * 4 + j;
            asm volatile("cp.async.cg.shared.global [%0], [%1], 16;"
                         :: "r"(dst + jj * 8192), "l"(g + jj * 4096) : "memory");
        }
    CP_COMMIT();
    #pragma unroll
    for (int p = 1; p < NPIECES; p += 2)
        #pragma unroll
        for (int j = 0; j < 4; ++j) {
            int jj = p * 4 + j;
            asm volatile("cp.async.cg.shared.global [%0], [%1], 16;"
                         :: "r"(dst + jj * 8192), "l"(g + jj * 4096) : "memory");
        }
    CP_COMMIT();
}

// 128 rows x 256 f32 -> f16 into SA, blocked SW128 (512 threads)
DINL void stage_x(const float* __restrict__ x, char* smem, int tid) {
    #pragma unroll
    for (int i = tid; i < 4096; i += 512) {
        int r = i >> 5, u = i & 31;
        const float4* src = (const float4*)(x + (size_t)r * 256 + u * 8);
        float4 v0 = src[0], v1 = src[1];
        __half2 h0 = __floats2half2_rn(v0.x, v0.y);
        __half2 h1 = __floats2half2_rn(v0.z, v0.w);
        __half2 h2 = __floats2half2_rn(v1.x, v1.y);
        __half2 h3 = __floats2half2_rn(v1.z, v1.w);
        int byte = ((r >> 3) + (u >> 3) * 16) * 1024 + (r & 7) * 128 + (u & 7) * 16;
        byte ^= (r & 7) << 4;
        uint4 pk;
        pk.x = *(unsigned*)&h0; pk.y = *(unsigned*)&h1;
        pk.z = *(unsigned*)&h2; pk.w = *(unsigned*)&h3;
        *(uint4*)(smem + cfg::SA + byte) = pk;
    }
}

// ---------- half-layer (8 k-steps) of 128x256 GEMM, warp tile 64x32 --------
// NP: 4 = full 256-col layer, 2 = reg layer (cols >= 96 dead -> wn >= 3 skip)
// KH: which K-half (0: k0 0..7 w/ acc init, 1: k0 8..15 accumulate)
template <int NP, int KH>
DINL void mma_half(unsigned aBase, unsigned bBase, float acc[4][4][4],
                   int lane, int wm, int wn) {
    if (KH == 0) {
        #pragma unroll
        for (int i = 0; i < 4; ++i)
            #pragma unroll
            for (int j = 0; j < 4; ++j)
                #pragma unroll
                for (int k = 0; k < 4; ++k) acc[i][j][k] = 0.f;
    }
    if (NP == 2 && wn >= 3) return;   // reg layer: cols >= 96 all dead

    const int la7 = lane & 7, lb3 = (lane >> 3) & 1, lb4 = (lane >> 4) & 1;
    unsigned rowA[4], rowB[2];
    #pragma unroll
    for (int mi = 0; mi < 4; ++mi) {
        int R = wm * 64 + mi * 16 + lb3 * 8 + la7;
        rowA[mi] = aBase + (unsigned)((R >> 3) * 1024 + la7 * 128);
    }
    const unsigned bsel = (wn >= 4) ? 65536u : 0u;
    #pragma unroll
    for (int np = 0; np < 2; ++np) {
        int R = (wn & 3) * 32 + np * 16 + lb4 * 8 + la7;
        rowB[np] = bBase + bsel + (unsigned)((R >> 3) * 1024 + la7 * 128);
    }
    #pragma unroll
    for (int kk = 0; kk < 8; ++kk) {
        int k0  = KH * 8 + kk;
        int qa  = 2 * k0 + lb4;
        int qbl = 2 * kk + lb3;
        unsigned ca = (unsigned)(((qa >> 3) << 14) + (((qa & 7) ^ la7) << 4));
        unsigned cb = (unsigned)((KH ? 32768 : 0) +
                                 ((qbl >> 3) << 14) + (((qbl & 7) ^ la7) << 4));
        unsigned a0[4], a1[4], a2[4], a3[4], b0[4], b1[4];
        ldm4(a0, rowA[0] + ca);
        ldm4(a1, rowA[1] + ca);
        ldm4(a2, rowA[2] + ca);
        ldm4(a3, rowA[3] + ca);
        ldm4(b0, rowB[0] + cb);
        ldm4(b1, rowB[1] + cb);
        mma4(acc[0][0], a0, b0[0], b0[1]); mma4(acc[0][1], a0, b0[2], b0[3]);
        mma4(acc[0][2], a0, b1[0], b1[1]); mma4(acc[0][3], a0, b1[2], b1[3]);
        mma4(acc[1][0], a1, b0[0], b0[1]); mma4(acc[1][1], a1, b0[2], b0[3]);
        mma4(acc[1][2], a1, b1[0], b1[1]); mma4(acc[1][3], a1, b1[2], b1[3]);
        mma4(acc[2][0], a2, b0[0], b0[1]); mma4(acc[2][1], a2, b0[2], b0[3]);
        mma4(acc[2][2], a2, b1[0], b1[1]); mma4(acc[2][3], a2, b1[2], b1[3]);
        mma4(acc[3][0], a3, b0[0], b0[1]); mma4(acc[3][1], a3, b0[2], b0[3]);
        mma4(acc[3][2], a3, b1[0], b1[1]); mma4(acc[3][3], a3, b1[2], b1[3]);
    }
}

// full layer: wait G1, sync, K-lo, wait G2, sync, K-hi
#define MMA_LAYER(NP, ABASE)                                         \
    do {                                                             \
        cp_wait<1>(); __syncthreads();                               \
        mma_half<NP, 0>(ABASE, sbm + SB, acc, lane, wm, wn);         \
        cp_wait<0>(); __syncthreads();                               \
        mma_half<NP, 1>(ABASE, sbm + SB, acc, lane, wm, wn);         \
        __syncthreads();                                             \
    } while (0)

// bias + relu -> f16 IN PLACE into SA (blocked SW128), full 256 cols
DINL void epi_hidden(const float acc[4][4][4], char* sOut, const float* bias,
                     int lane, int wm, int wn) {
    #pragma unroll
    for (int mi = 0; mi < 4; ++mi) {
        int R = wm * 64 + mi * 16 + (lane >> 2);
        #pragma unroll
        for (int nj = 0; nj < 4; ++nj) {
            int C = wn * 32 + nj * 8 + (lane & 3) * 2;
            float b0 = bias[C], b1 = bias[C + 1];
            __half2 lo = __floats2half2_rn(fmaxf(acc[mi][nj][0] + b0, 0.f),
                                           fmaxf(acc[mi][nj][1] + b1, 0.f));
            __half2 hi = __floats2half2_rn(fmaxf(acc[mi][nj][2] + b0, 0.f),
                                           fmaxf(acc[mi][nj][3] + b1, 0.f));
            int byte = ((R >> 3) + (C >> 6) * 16) * 1024 + (R & 7) * 128 + (C & 63) * 2;
            byte ^= (R & 7) << 4;
            *(__half2*)(sOut + byte) = lo;
            *(__half2*)(sOut + byte + 1024) = hi;
        }
    }
}

// reg-pred epilogue: fp32 (cols < 68) IN PLACE into SA (stride 68) + global
DINL void epi_reg(const float acc[4][4][4], float* sReg, const float* bias,
                  float* __restrict__ gReg, int row0, int lane, int wm, int wn) {
    if (wn >= 3) return;
    #pragma unroll
    for (int mi = 0; mi < 4; ++mi) {
        int R = wm * 64 + mi * 16 + (lane >> 2);
        #pragma unroll
        for (int nj = 0; nj < 4; ++nj) {
            int C = wn * 32 + nj * 8 + (lane & 3) * 2;
            if (C < 68) {
                float b0 = bias[C], b1 = bias[C + 1];
                float2 lo = make_float2(acc[mi][nj][0] + b0, acc[mi][nj][1] + b1);
                float2 hi = make_float2(acc[mi][nj][2] + b0, acc[mi][nj][3] + b1);
                *(float2*)(sReg + R * 68 + C) = lo;
                *(float2*)(sReg + (R + 8) * 68 + C) = hi;
                *(float2*)(gReg + (size_t)(row0 + R) * 68 + C) = lo;
                *(float2*)(gReg + (size_t)(row0 + R + 8) * 68 + C) = hi;
            }
        }
    }
}

// ------------------------------ main kernel --------------------------------
__global__ __launch_bounds__(512, 1)
void gfocal_head_kernel(const float* __restrict__ x,
                        const float* __restrict__ cb1, const float* __restrict__ cb2,
                        const float* __restrict__ cw3, const float* __restrict__ cb3,
                        const float* __restrict__ rb1, const float* __restrict__ rb2,
                        const float* __restrict__ rb3,
                        const float* __restrict__ qw1, const float* __restrict__ qb1,
                        const float* __restrict__ qw2, const float* __restrict__ qb2,
                        float* __restrict__ out) {
    using namespace cfg;
    extern __shared__ char smem[];
    const unsigned sbm = smem_u32(smem);
    const int tid = threadIdx.x, w = tid >> 5, lane = tid & 31;
    const int wm = w >> 3, wn = w & 7;
    const int row0 = blockIdx.x * TM;

    float* out_cls = out;
    float* out_box = out + (size_t)P;
    float* out_reg = out + (size_t)P * 5;

    const float* bias = (const float*)(smem + SBIAS);

    // ---- prolog: prefetch L0 weights (2 groups), small weights, stage X ----
    stage_layer2<4>(0, sbm, tid);
    if (tid < 256) {
        float* fb = (float*)(smem + SBIAS);
        fb[tid] = rb1[tid]; fb[256 + tid] = rb2[tid];
        fb[512 + tid] = cb1[tid]; fb[768 + tid] = cb2[tid];
        if (tid < 68) fb[1024 + tid] = rb3[tid];
        ((float*)(smem + SCW3))[tid] = cw3[tid];
        if (tid < 64) { ((float*)(smem + SQB1))[tid] = qb1[tid];
                        ((float*)(smem + SQW2))[tid] = qw2[tid]; }
        if (tid == 0) { ((float*)(smem + SSC))[0] = qb2[0];
                        ((float*)(smem + SSC))[1] = cb3[0]; }
    }
    {
        float* q1 = (float*)(smem + SQW1);
        for (int i = tid; i < 1280; i += 512) q1[i] = qw1[i];
    }
    stage_x(x + (size_t)row0 * 256, smem, tid);

    float acc[4][4][4];

    // ---------------- regression branch ----------------
    MMA_LAYER(4, sbm + SA);                                // X @ rw1^T
    stage_layer2<4>(4, sbm, tid);                          // prefetch rw2
    epi_hidden(acc, smem + SA, bias, lane, wm, wn);        // SA = h1r

    MMA_LAYER(4, sbm + SA);                                // h1 @ rw2^T
    stage_layer2<2>(8, sbm, tid);                          // prefetch rw3
    epi_hidden(acc, smem + SA, bias + 256, lane, wm, wn);  // SA = h2r

    MMA_LAYER(2, sbm + SA);                                // h2 @ rw3^T
    stage_layer2<4>(10, sbm, tid);                         // prefetch cw1
    epi_reg(acc, (float*)(smem + SA), bias + 1024, out_reg, row0, lane, wm, wn);
    __syncthreads();

    // ---- stats: softmax, box, top-4 -> sStat (thread = (row, direction)) ----
    {
        int row = tid >> 2, d = tid & 3;
        const float* rp = (const float*)(smem + SA) + row * 68 + d * 17;
        float* sStat = (float*)(smem + SSTAT);
        float pb[17];
        float mx = -1e30f;
        #pragma unroll
        for (int b = 0; b < 17; ++b) { pb[b] = rp[b]; mx = fmaxf(mx, pb[b]); }
        float s = 0.f, sbi = 0.f;
        #pragma unroll
        for (int b = 0; b < 17; ++b) {
            float e = __expf(pb[b] - mx);
            pb[b] = e; s += e; sbi += e * (float)b;
        }
        float inv = 1.f / s;
        out_box[(size_t)(row0 + row) * 4 + d] = sbi * inv * (1.f / 16.f);
        unsigned mask = 0; float tsum = 0.f;
        #pragma unroll
        for (int j = 0; j < 4; ++j) {
            float m = -1e30f; int mi = 0;
            #pragma unroll
            for (int b = 0; b < 17; ++b) {
                bool ok = !((mask >> b) & 1u) && (pb[b] > m);
                if (ok) { m = pb[b]; mi = b; }
            }
            mask |= (1u << mi);
            tsum += m;
            sStat[row * 21 + d * 5 + j] = m * inv;
        }
        sStat[row * 21 + d * 5 + 4] = tsum * inv * 0.25f;
    }
    __syncthreads();

    // ---- quality (tid<128) + restage X for cls (all threads) ----
    if (tid < TM) {
        const float* st = (const float*)(smem + SSTAT) + tid * 21;
        const float* q1 = (const float*)(smem + SQW1);
        const float* qb = (const float*)(smem + SQB1);
        const float* q2 = (const float*)(smem + SQW2);
        float q = ((const float*)(smem + SSC))[0];
        #pragma unroll 4
        for (int o = 0; o < 64; ++o) {
            float h = qb[o];
            #pragma unroll
            for (int c = 0; c < 20; ++c) h += q1[o * 20 + c] * st[c];
            q += q2[o] * fmaxf(h, 0.f);
        }
        ((float*)(smem + SQUAL))[tid] = 1.f / (1.f + __expf(-q));
    }
    stage_x(x + (size_t)row0 * 256, smem, tid);            // SA = X again

    // ---------------- classification branch ----------------
    MMA_LAYER(4, sbm + SA);                                // X @ cw1^T
    stage_layer2<4>(14, sbm, tid);                         // prefetch cw2
    epi_hidden(acc, smem + SA, bias + 512, lane, wm, wn);  // SA = h1c

    MMA_LAYER(4, sbm + SA);                                // h1 @ cw2^T
    epi_hidden(acc, smem + SA, bias + 768, lane, wm, wn);  // SA = h2c
    __syncthreads();

    // ---- cls L3: dot(h2c, cw3) + cb3, sigmoid, * quality ----
    if (tid < TM) {
        int r = tid, r7 = r & 7;
        unsigned rbase = (unsigned)((r >> 3) * 1024 + r7 * 128);
        const float* w3 = (const float*)(smem + SCW3);
        float a = ((const float*)(smem + SSC))[1];
        #pragma unroll
        for (int cg = 0; cg < 4; ++cg) {
            #pragma unroll
            for (int u = 0; u < 8; ++u) {
                const __half2* p = (const __half2*)(smem + SA + rbase +
                                                    cg * 16384 + ((u ^ r7) << 4));
                const float* wseg = w3 + cg * 64 + u * 8;
                #pragma unroll
                for (int j = 0; j < 4; ++j) {
                    float2 v = __half22float2(p[j]);
                    a += v.x * wseg[2 * j] + v.y * wseg[2 * j + 1];
                }
            }
        }
        float csig = 1.f / (1.f + __expf(-a));
        out_cls[row0 + r] = csig * ((const float*)(smem + SQUAL))[r];
    }
}

// ------------------------------ launcher -----------------------------------
extern "C" void kernel_launch(void* const* d_in, const int* in_sizes, int n_in,
                              void* d_out, int out_size) {
    const float* x   = (const float*)d_in[0];
    const float* cw1 = (const float*)d_in[1];
    const float* cb1 = (const float*)d_in[2];
    const float* cw2 = (const float*)d_in[3];
    const float* cb2 = (const float*)d_in[4];
    const float* cw3 = (const float*)d_in[5];
    const float* cb3 = (const float*)d_in[6];
    const float* rw1 = (const float*)d_in[7];
    const float* rb1 = (const float*)d_in[8];
    const float* rw2 = (const float*)d_in[9];
    const float* rb2 = (const float*)d_in[10];
    const float* rw3 = (const float*)d_in[11];
    const float* rb3 = (const float*)d_in[12];
    const float* qw1 = (const float*)d_in[13];
    const float* qb1 = (const float*)d_in[14];
    const float* qw2 = (const float*)d_in[15];
    const float* qb2 = (const float*)d_in[16];
    float* out = (float*)d_out;

    cudaFuncSetAttribute(gfocal_head_kernel,
                         cudaFuncAttributeMaxDynamicSharedMemorySize, cfg::SMEMB);

    convert_weights_kernel<<<cfg::NH * cfg::HHALF / 512, 512>>>(cw1, cw2, rw1, rw2, rw3);
    gfocal_head_kernel<<<cfg::NBLK, 512, cfg::SMEMB>>>(
        x, cb1, cb2, cw3, cb3, rb1, rb2, rb3, qw1, qb1, qw2, qb2, out);
}

// round 15
// speedup vs baseline: 1.3405x; 1.0329x over previous
#include <cuda_runtime.h>
#include <cuda_fp16.h>

#define DINL __device__ __forceinline__

// ---------------------------------------------------------------------------
// GFocalV2 head (sm_103): fused 3-layer MLPs via mma.sync.m16n8k16 + ldmatrix.
// 512 threads / 16 warps, warp tile 64x32, full 128x256 layer per sweep,
// layer weights fully resident, in-place SA activations. Round 15: manual
// software pipeline — fragments for k0+1 prefetched (double-buffered in regs)
// before k0's MMAs, hiding ldmatrix latency.
// ---------------------------------------------------------------------------

namespace cfg {
constexpr int P    = 32 * 96 * 96;   // 294912
constexpr int TM   = 128;            // rows per CTA
constexpr int NBLK = P / TM;         // 2304
constexpr int HHALF = 16384;         // halves per 32KB piece
constexpr int NH   = 18;             // pieces in weight cache

// dynamic smem (bytes)
constexpr int SA    = 0;             // 128x256 f16 blocked SW128 (64 KB), in-place I/O
constexpr int SB    = 65536;         // 4 x 32KB weight pieces (full layer)
constexpr int SBIAS = 196608;        // rb1 +0, rb2 +1024, cb1 +2048, cb2 +3072, rb3 +4096
constexpr int SSTAT = SBIAS + 4608;  // 128*21 f32
constexpr int SQW1  = SSTAT + 10752;
constexpr int SQB1  = SQW1 + 5120;
constexpr int SQW2  = SQB1 + 256;
constexpr int SCW3  = SQW2 + 256;
constexpr int SQUAL = SCW3 + 1024;
constexpr int SSC   = SQUAL + 512;
constexpr int SMEMB = SSC + 16;      // ~219 KB
}  // namespace cfg

__device__ __align__(16) __half g_wh[cfg::NH * cfg::HHALF];

// --------------------- weight fp32 -> fp16 pre-swizzled --------------------
__global__ void convert_weights_kernel(const float* __restrict__ cw1,
                                       const float* __restrict__ cw2,
                                       const float* __restrict__ rw1,
                                       const float* __restrict__ rw2,
                                       const float* __restrict__ rw3) {
    int i = blockIdx.x * 512 + threadIdx.x;   // 0..294911
    int sc = i >> 15;
    int e  = i & 32767;
    int r  = e >> 8, c = e & 255;
    float v = 0.f;
    if (sc < 2)       v = rw1[(sc * 128 + r) * 256 + c];
    else if (sc < 4)  v = rw2[((sc - 2) * 128 + r) * 256 + c];
    else if (sc < 5)  { if (r < 68) v = rw3[r * 256 + c]; }
    else if (sc < 7)  v = cw1[((sc - 5) * 128 + r) * 256 + c];
    else              v = cw2[((sc - 7) * 128 + r) * 256 + c];
    int byte = ((r >> 3) + (c >> 6) * 16) * 1024 + (r & 7) * 128 + (c & 63) * 2;
    byte ^= (r & 7) << 4;
    g_wh[sc * 32768 + (byte >> 1)] = __float2half(v);
}

// ------------------------------ PTX helpers --------------------------------
DINL unsigned smem_u32(const void* p) {
    unsigned a;
    asm("{ .reg .u64 t; cvta.to.shared.u64 t, %1; cvt.u32.u64 %0, t; }"
        : "=r"(a) : "l"(p));
    return a;
}
DINL void ldm4(unsigned r[4], unsigned addr) {
    asm volatile("ldmatrix.sync.aligned.m8n8.x4.shared.b16 {%0,%1,%2,%3}, [%4];"
                 : "=r"(r[0]), "=r"(r[1]), "=r"(r[2]), "=r"(r[3]) : "r"(addr));
}
DINL void mma4(float d[4], const unsigned a[4], unsigned b0, unsigned b1) {
    asm volatile(
        "mma.sync.aligned.m16n8k16.row.col.f32.f16.f16.f32 "
        "{%0,%1,%2,%3}, {%4,%5,%6,%7}, {%8,%9}, {%0,%1,%2,%3};\n"
        : "+f"(d[0]), "+f"(d[1]), "+f"(d[2]), "+f"(d[3])
        : "r"(a[0]), "r"(a[1]), "r"(a[2]), "r"(a[3]), "r"(b0), "r"(b1));
}
#define CP_COMMIT() asm volatile("cp.async.commit_group;" ::: "memory")
template <int N> DINL void cp_wait() {
    asm volatile("cp.async.wait_group %0;" :: "n"(N) : "memory");
}

// ----------------------------- staging -------------------------------------
DINL void stage_layer(int h0, int npieces, unsigned sbm, int tid) {
    const __half* g = g_wh + (size_t)h0 * cfg::HHALF + tid * 8;
    unsigned dst = sbm + cfg::SB + tid * 16;
    for (int j = 0; j < npieces * 4; ++j)
        asm volatile("cp.async.cg.shared.global [%0], [%1], 16;"
                     :: "r"(dst + j * 8192), "l"(g + j * 4096) : "memory");
    CP_COMMIT();
}

// 128 rows x 256 f32 -> f16 into SA, blocked SW128 (512 threads)
DINL void stage_x(const float* __restrict__ x, char* smem, int tid) {
    #pragma unroll
    for (int i = tid; i < 4096; i += 512) {
        int r = i >> 5, u = i & 31;
        const float4* src = (const float4*)(x + (size_t)r * 256 + u * 8);
        float4 v0 = src[0], v1 = src[1];
        __half2 h0 = __floats2half2_rn(v0.x, v0.y);
        __half2 h1 = __floats2half2_rn(v0.z, v0.w);
        __half2 h2 = __floats2half2_rn(v1.x, v1.y);
        __half2 h3 = __floats2half2_rn(v1.z, v1.w);
        int byte = ((r >> 3) + (u >> 3) * 16) * 1024 + (r & 7) * 128 + (u & 7) * 16;
        byte ^= (r & 7) << 4;
        uint4 pk;
        pk.x = *(unsigned*)&h0; pk.y = *(unsigned*)&h1;
        pk.z = *(unsigned*)&h2; pk.w = *(unsigned*)&h3;
        *(uint4*)(smem + cfg::SA + byte) = pk;
    }
}

// ------- full-layer 128x256 GEMM, warp tile 64x32, SW-pipelined k-loop ------
// NP: 4 = full 256-col layer, 2 = reg layer (cols >= 96 dead -> wn >= 3 skip)
template <int NP>
DINL void mma_layer_pl(unsigned aBase, unsigned bBase, float acc[4][4][4],
                       int lane, int wm, int wn) {
    #pragma unroll
    for (int i = 0; i < 4; ++i)
        #pragma unroll
        for (int j = 0; j < 4; ++j)
            #pragma unroll
            for (int k = 0; k < 4; ++k) acc[i][j][k] = 0.f;
    if (NP == 2 && wn >= 3) return;   // reg layer: cols >= 96 all dead

    const int la7 = lane & 7, lb3 = (lane >> 3) & 1, lb4 = (lane >> 4) & 1;
    // rowA[mi] = rowA0 + mi*2048 ; rowB[np] = rowB0 + np*2048 (compile-time)
    const unsigned rowA0 = aBase +
        (unsigned)(((wm * 64 + lb3 * 8 + la7) >> 3) * 1024 + la7 * 128);
    const unsigned bsel = (wn >= 4) ? 65536u : 0u;
    const unsigned rowB0 = bBase + bsel +
        (unsigned)((((wn & 3) * 32 + lb4 * 8 + la7) >> 3) * 1024 + la7 * 128);

    unsigned af[2][4][4];   // [slot][mi][frag]
    unsigned bf[2][2][4];   // [slot][np][frag]

#define LOADK(K0, S)                                                           \
    {                                                                          \
        const int qa  = 2 * (K0) + lb4;                                        \
        const int qbl = 2 * ((K0) & 7) + lb3;                                  \
        const unsigned ca = (unsigned)(((qa >> 3) << 14) +                     \
                                       (((qa & 7) ^ la7) << 4));               \
        const unsigned cb = (unsigned)((((K0) >= 8) ? 32768 : 0) +             \
                                       ((qbl >> 3) << 14) +                    \
                                       (((qbl & 7) ^ la7) << 4));              \
        ldm4(af[S][0], rowA0 + ca);                                            \
        ldm4(af[S][1], rowA0 + 2048 + ca);                                     \
        ldm4(af[S][2], rowA0 + 4096 + ca);                                     \
        ldm4(af[S][3], rowA0 + 6144 + ca);                                     \
        ldm4(bf[S][0], rowB0 + cb);                                            \
        ldm4(bf[S][1], rowB0 + 2048 + cb);                                     \
    }

    LOADK(0, 0);
    #pragma unroll
    for (int k0 = 0; k0 < 16; ++k0) {
        const int cur = k0 & 1;
        if (k0 < 15) {
            const int nxt = cur ^ 1;
            LOADK(k0 + 1, nxt);
        }
        #pragma unroll
        for (int mi = 0; mi < 4; ++mi) {
            mma4(acc[mi][0], af[cur][mi], bf[cur][0][0], bf[cur][0][1]);
            mma4(acc[mi][1], af[cur][mi], bf[cur][0][2], bf[cur][0][3]);
            mma4(acc[mi][2], af[cur][mi], bf[cur][1][0], bf[cur][1][1]);
            mma4(acc[mi][3], af[cur][mi], bf[cur][1][2], bf[cur][1][3]);
        }
    }
#undef LOADK
}

// bias + relu -> f16 IN PLACE into SA (blocked SW128), full 256 cols
DINL void epi_hidden(const float acc[4][4][4], char* sOut, const float* bias,
                     int lane, int wm, int wn) {
    #pragma unroll
    for (int mi = 0; mi < 4; ++mi) {
        int R = wm * 64 + mi * 16 + (lane >> 2);
        #pragma unroll
        for (int nj = 0; nj < 4; ++nj) {
            int C = wn * 32 + nj * 8 + (lane & 3) * 2;
            float b0 = bias[C], b1 = bias[C + 1];
            __half2 lo = __floats2half2_rn(fmaxf(acc[mi][nj][0] + b0, 0.f),
                                           fmaxf(acc[mi][nj][1] + b1, 0.f));
            __half2 hi = __floats2half2_rn(fmaxf(acc[mi][nj][2] + b0, 0.f),
                                           fmaxf(acc[mi][nj][3] + b1, 0.f));
            int byte = ((R >> 3) + (C >> 6) * 16) * 1024 + (R & 7) * 128 + (C & 63) * 2;
            byte ^= (R & 7) << 4;
            *(__half2*)(sOut + byte) = lo;
            *(__half2*)(sOut + byte + 1024) = hi;
        }
    }
}

// reg-pred epilogue: fp32 (cols < 68) IN PLACE into SA (stride 68) + global
DINL void epi_reg(const float acc[4][4][4], float* sReg, const float* bias,
                  float* __restrict__ gReg, int row0, int lane, int wm, int wn) {
    if (wn >= 3) return;
    #pragma unroll
    for (int mi = 0; mi < 4; ++mi) {
        int R = wm * 64 + mi * 16 + (lane >> 2);
        #pragma unroll
        for (int nj = 0; nj < 4; ++nj) {
            int C = wn * 32 + nj * 8 + (lane & 3) * 2;
            if (C < 68) {
                float b0 = bias[C], b1 = bias[C + 1];
                float2 lo = make_float2(acc[mi][nj][0] + b0, acc[mi][nj][1] + b1);
                float2 hi = make_float2(acc[mi][nj][2] + b0, acc[mi][nj][3] + b1);
                *(float2*)(sReg + R * 68 + C) = lo;
                *(float2*)(sReg + (R + 8) * 68 + C) = hi;
                *(float2*)(gReg + (size_t)(row0 + R) * 68 + C) = lo;
                *(float2*)(gReg + (size_t)(row0 + R + 8) * 68 + C) = hi;
            }
        }
    }
}

// ------------------------------ main kernel --------------------------------
__global__ __launch_bounds__(512, 1)
void gfocal_head_kernel(const float* __restrict__ x,
                        const float* __restrict__ cb1, const float* __restrict__ cb2,
                        const float* __restrict__ cw3, const float* __restrict__ cb3,
                        const float* __restrict__ rb1, const float* __restrict__ rb2,
                        const float* __restrict__ rb3,
                        const float* __restrict__ qw1, const float* __restrict__ qb1,
                        const float* __restrict__ qw2, const float* __restrict__ qb2,
                        float* __restrict__ out) {
    using namespace cfg;
    extern __shared__ char smem[];
    const unsigned sbm = smem_u32(smem);
    const int tid = threadIdx.x, w = tid >> 5, lane = tid & 31;
    const int wm = w >> 3, wn = w & 7;
    const int row0 = blockIdx.x * TM;

    float* out_cls = out;
    float* out_box = out + (size_t)P;
    float* out_reg = out + (size_t)P * 5;

    const float* bias = (const float*)(smem + SBIAS);

    // ---- prolog: prefetch L0 weights, small weights, stage X ----
    stage_layer(0, 4, sbm, tid);
    if (tid < 256) {
        float* fb = (float*)(smem + SBIAS);
        fb[tid] = rb1[tid]; fb[256 + tid] = rb2[tid];
        fb[512 + tid] = cb1[tid]; fb[768 + tid] = cb2[tid];
        if (tid < 68) fb[1024 + tid] = rb3[tid];
        ((float*)(smem + SCW3))[tid] = cw3[tid];
        if (tid < 64) { ((float*)(smem + SQB1))[tid] = qb1[tid];
                        ((float*)(smem + SQW2))[tid] = qw2[tid]; }
        if (tid == 0) { ((float*)(smem + SSC))[0] = qb2[0];
                        ((float*)(smem + SSC))[1] = cb3[0]; }
    }
    {
        float* q1 = (float*)(smem + SQW1);
        for (int i = tid; i < 1280; i += 512) q1[i] = qw1[i];
    }
    stage_x(x + (size_t)row0 * 256, smem, tid);

    float acc[4][4][4];

    // ---------------- regression branch ----------------
    cp_wait<0>(); __syncthreads();
    mma_layer_pl<4>(sbm + SA, sbm + SB, acc, lane, wm, wn);   // X @ rw1^T
    __syncthreads();
    stage_layer(4, 4, sbm, tid);                              // prefetch rw2
    epi_hidden(acc, smem + SA, bias, lane, wm, wn);           // SA = h1r

    cp_wait<0>(); __syncthreads();
    mma_layer_pl<4>(sbm + SA, sbm + SB, acc, lane, wm, wn);   // h1 @ rw2^T
    __syncthreads();
    stage_layer(8, 2, sbm, tid);                              // prefetch rw3
    epi_hidden(acc, smem + SA, bias + 256, lane, wm, wn);     // SA = h2r

    cp_wait<0>(); __syncthreads();
    mma_layer_pl<2>(sbm + SA, sbm + SB, acc, lane, wm, wn);   // h2 @ rw3^T
    __syncthreads();
    stage_layer(10, 4, sbm, tid);                             // prefetch cw1
    epi_reg(acc, (float*)(smem + SA), bias + 1024, out_reg, row0, lane, wm, wn);
    __syncthreads();

    // ---- stats: softmax, box, top-4 -> sStat (thread = (row, direction)) ----
    {
        int row = tid >> 2, d = tid & 3;
        const float* rp = (const float*)(smem + SA) + row * 68 + d * 17;
        float* sStat = (float*)(smem + SSTAT);
        float pb[17];
        float mx = -1e30f;
        #pragma unroll
        for (int b = 0; b < 17; ++b) { pb[b] = rp[b]; mx = fmaxf(mx, pb[b]); }
        float s = 0.f, sbi = 0.f;
        #pragma unroll
        for (int b = 0; b < 17; ++b) {
            float e = __expf(pb[b] - mx);
            pb[b] = e; s += e; sbi += e * (float)b;
        }
        float inv = 1.f / s;
        out_box[(size_t)(row0 + row) * 4 + d] = sbi * inv * (1.f / 16.f);
        unsigned mask = 0; float tsum = 0.f;
        #pragma unroll
        for (int j = 0; j < 4; ++j) {
            float m = -1e30f; int mi = 0;
            #pragma unroll
            for (int b = 0; b < 17; ++b) {
                bool ok = !((mask >> b) & 1u) && (pb[b] > m);
                if (ok) { m = pb[b]; mi = b; }
            }
            mask |= (1u << mi);
            tsum += m;
            sStat[row * 21 + d * 5 + j] = m * inv;
        }
        sStat[row * 21 + d * 5 + 4] = tsum * inv * 0.25f;
    }
    __syncthreads();

    // ---- quality (tid<128) + restage X for cls (all threads) ----
    if (tid < TM) {
        const float* st = (const float*)(smem + SSTAT) + tid * 21;
        const float* q1 = (const float*)(smem + SQW1);
        const float* qb = (const float*)(smem + SQB1);
        const float* q2 = (const float*)(smem + SQW2);
        float q = ((const float*)(smem + SSC))[0];
        #pragma unroll 4
        for (int o = 0; o < 64; ++o) {
            float h = qb[o];
            #pragma unroll
            for (int c = 0; c < 20; ++c) h += q1[o * 20 + c] * st[c];
            q += q2[o] * fmaxf(h, 0.f);
        }
        ((float*)(smem + SQUAL))[tid] = 1.f / (1.f + __expf(-q));
    }
    stage_x(x + (size_t)row0 * 256, smem, tid);               // SA = X again

    // ---------------- classification branch ----------------
    cp_wait<0>(); __syncthreads();
    mma_layer_pl<4>(sbm + SA, sbm + SB, acc, lane, wm, wn);   // X @ cw1^T
    __syncthreads();
    stage_layer(14, 4, sbm, tid);                             // prefetch cw2
    epi_hidden(acc, smem + SA, bias + 512, lane, wm, wn);     // SA = h1c

    cp_wait<0>(); __syncthreads();
    mma_layer_pl<4>(sbm + SA, sbm + SB, acc, lane, wm, wn);   // h1 @ cw2^T
    __syncthreads();
    epi_hidden(acc, smem + SA, bias + 768, lane, wm, wn);     // SA = h2c
    __syncthreads();

    // ---- cls L3: dot(h2c, cw3) + cb3, sigmoid, * quality ----
    if (tid < TM) {
        int r = tid, r7 = r & 7;
        unsigned rbase = (unsigned)((r >> 3) * 1024 + r7 * 128);
        const float* w3 = (const float*)(smem + SCW3);
        float a = ((const float*)(smem + SSC))[1];
        #pragma unroll
        for (int cg = 0; cg < 4; ++cg) {
            #pragma unroll
            for (int u = 0; u < 8; ++u) {
                const __half2* p = (const __half2*)(smem + SA + rbase +
                                                    cg * 16384 + ((u ^ r7) << 4));
                const float* wseg = w3 + cg * 64 + u * 8;
                #pragma unroll
                for (int j = 0; j < 4; ++j) {
                    float2 v = __half22float2(p[j]);
                    a += v.x * wseg[2 * j] + v.y * wseg[2 * j + 1];
                }
            }
        }
        float csig = 1.f / (1.f + __expf(-a));
        out_cls[row0 + r] = csig * ((const float*)(smem + SQUAL))[r];
    }
}

// ------------------------------ launcher -----------------------------------
extern "C" void kernel_launch(void* const* d_in, const int* in_sizes, int n_in,
                              void* d_out, int out_size) {
    const float* x   = (const float*)d_in[0];
    const float* cw1 = (const float*)d_in[1];
    const float* cb1 = (const float*)d_in[2];
    const float* cw2 = (const float*)d_in[3];
    const float* cb2 = (const float*)d_in[4];
    const float* cw3 = (const float*)d_in[5];
    const float* cb3 = (const float*)d_in[6];
    const float* rw1 = (const float*)d_in[7];
    const float* rb1 = (const float*)d_in[8];
    const float* rw2 = (const float*)d_in[9];
    const float* rb2 = (const float*)d_in[10];
    const float* rw3 = (const float*)d_in[11];
    const float* rb3 = (const float*)d_in[12];
    const float* qw1 = (const float*)d_in[13];
    const float* qb1 = (const float*)d_in[14];
    const float* qw2 = (const float*)d_in[15];
    const float* qb2 = (const float*)d_in[16];
    float* out = (float*)d_out;

    cudaFuncSetAttribute(gfocal_head_kernel,
                         cudaFuncAttributeMaxDynamicSharedMemorySize, cfg::SMEMB);

    convert_weights_kernel<<<cfg::NH * cfg::HHALF / 512, 512>>>(cw1, cw2, rw1, rw2, rw3);
    gfocal_head_kernel<<<cfg::NBLK, 512, cfg::SMEMB>>>(
        x, cb1, cb2, cw3, cb3, rb1, rb2, rb3, qw1, qb1, qw2, qb2, out);
}